// round 2
// baseline (speedup 1.0000x reference)
#include <cuda_runtime.h>

// HydraGNN: 2x SAGEConv(mean) + MLP head, fp32.
// Strategy: build CSR (counting sort by dst) per launch, atomic-free warp-per-node
// mean aggregation (L2-resident gathers), shared-memory-weight fused update GEMMs.

#define NN 50000
#define NE 800000
#define CHUNK 512
#define NCHUNK ((NN + CHUNK - 1) / CHUNK)   // 98

__device__ int g_counts[NN];
__device__ int g_row_start[NN + 1];
__device__ int g_row_fill[NN];
__device__ int g_csr_src[NE];
__device__ int g_part[NCHUNK];
__device__ __align__(16) float g_mean[NN * 64];
__device__ __align__(16) float g_h1[NN * 64];

// ---------------------------------------------------------------- CSR build
__global__ void k_zero_counts() {
    int i = blockIdx.x * blockDim.x + threadIdx.x;
    if (i < NN) g_counts[i] = 0;
}

__global__ void k_hist(const int* __restrict__ dst) {
    int e = blockIdx.x * blockDim.x + threadIdx.x;
    if (e < NE) atomicAdd(&g_counts[dst[e]], 1);
}

__global__ void k_chunk_sums() {
    __shared__ int sh[CHUNK];
    int i = blockIdx.x * CHUNK + threadIdx.x;
    sh[threadIdx.x] = (i < NN) ? g_counts[i] : 0;
    __syncthreads();
    for (int off = CHUNK >> 1; off > 0; off >>= 1) {
        if (threadIdx.x < off) sh[threadIdx.x] += sh[threadIdx.x + off];
        __syncthreads();
    }
    if (threadIdx.x == 0) g_part[blockIdx.x] = sh[0];
}

__global__ void k_scan_part() {   // 1 block, 128 threads (NCHUNK=98 <= 128)
    __shared__ int sh[128];
    int v = (threadIdx.x < NCHUNK) ? g_part[threadIdx.x] : 0;
    sh[threadIdx.x] = v;
    __syncthreads();
    for (int off = 1; off < 128; off <<= 1) {
        int t = (threadIdx.x >= off) ? sh[threadIdx.x - off] : 0;
        __syncthreads();
        sh[threadIdx.x] += t;
        __syncthreads();
    }
    if (threadIdx.x < NCHUNK) g_part[threadIdx.x] = sh[threadIdx.x] - v;  // exclusive
    if (threadIdx.x == 0) g_row_start[NN] = NE;
}

__global__ void k_scan_chunks() {
    __shared__ int sh[CHUNK];
    int i = blockIdx.x * CHUNK + threadIdx.x;
    int v = (i < NN) ? g_counts[i] : 0;
    sh[threadIdx.x] = v;
    __syncthreads();
    for (int off = 1; off < CHUNK; off <<= 1) {
        int t = (threadIdx.x >= off) ? sh[threadIdx.x - off] : 0;
        __syncthreads();
        sh[threadIdx.x] += t;
        __syncthreads();
    }
    if (i < NN) {
        int excl = sh[threadIdx.x] - v + g_part[blockIdx.x];
        g_row_start[i] = excl;
        g_row_fill[i]  = excl;
    }
}

__global__ void k_scatter(const int* __restrict__ src, const int* __restrict__ dst) {
    int e = blockIdx.x * blockDim.x + threadIdx.x;
    if (e < NE) {
        int p = atomicAdd(&g_row_fill[dst[e]], 1);
        g_csr_src[p] = src[e];
    }
}

// ---------------------------------------------------------- mean aggregation
// One warp per node; lane handles channels {lane, lane+32}. Fully coalesced
// 2x128B gathers per edge, L2-resident, no atomics, deterministic per order.
__device__ __forceinline__ void agg_impl(const float* __restrict__ feat,
                                         float* __restrict__ outm,
                                         int w, int lane) {
    int s = g_row_start[w], e = g_row_start[w + 1];
    float a0 = 0.f, a1 = 0.f;
    int j = s;
    // 2-way unrolled to expose MLP
    for (; j + 1 < e; j += 2) {
        int s0 = g_csr_src[j];
        int s1 = g_csr_src[j + 1];
        const float* r0 = feat + (size_t)s0 * 64;
        const float* r1 = feat + (size_t)s1 * 64;
        float v0a = r0[lane], v0b = r0[lane + 32];
        float v1a = r1[lane], v1b = r1[lane + 32];
        a0 += v0a + v1a;
        a1 += v0b + v1b;
    }
    if (j < e) {
        const float* r = feat + (size_t)g_csr_src[j] * 64;
        a0 += r[lane];
        a1 += r[lane + 32];
    }
    float inv = 1.0f / fmaxf((float)(e - s), 1.0f);
    outm[(size_t)w * 64 + lane]      = a0 * inv;
    outm[(size_t)w * 64 + lane + 32] = a1 * inv;
}

__global__ void k_aggregate1(const float* __restrict__ x) {
    int w = (blockIdx.x * blockDim.x + threadIdx.x) >> 5;
    if (w >= NN) return;
    agg_impl(x, g_mean, w, threadIdx.x & 31);
}

__global__ void k_aggregate2() {
    int w = (blockIdx.x * blockDim.x + threadIdx.x) >> 5;
    if (w >= NN) return;
    agg_impl(g_h1, g_mean, w, threadIdx.x & 31);
}

// ------------------------------------------------------------- update GEMMs
// h1 = relu(mean @ w1_l + x @ w1_r + b1), thread-per-node, weights in shared
// (warp-uniform broadcast loads), 64 fp32 accumulators in registers.
__global__ __launch_bounds__(128) void k_update1(const float* __restrict__ x,
                                                 const float* __restrict__ wl,
                                                 const float* __restrict__ wr,
                                                 const float* __restrict__ b) {
    __shared__ float s_wl[64 * 64], s_wr[64 * 64], s_b[64];
    for (int idx = threadIdx.x; idx < 4096; idx += 128) {
        s_wl[idx] = wl[idx];
        s_wr[idx] = wr[idx];
    }
    if (threadIdx.x < 64) s_b[threadIdx.x] = b[threadIdx.x];
    __syncthreads();

    int i = blockIdx.x * blockDim.x + threadIdx.x;
    if (i >= NN) return;
    const float* m  = g_mean + (size_t)i * 64;
    const float* xi = x      + (size_t)i * 64;

    float acc[64];
#pragma unroll
    for (int j = 0; j < 64; j++) acc[j] = s_b[j];

    for (int kb = 0; kb < 64; kb += 8) {
        float mr[8], xr[8];
        *(float4*)(mr)     = *(const float4*)(m + kb);
        *(float4*)(mr + 4) = *(const float4*)(m + kb + 4);
        *(float4*)(xr)     = *(const float4*)(xi + kb);
        *(float4*)(xr + 4) = *(const float4*)(xi + kb + 4);
#pragma unroll
        for (int kk = 0; kk < 8; kk++) {
            float mv = mr[kk], xv = xr[kk];
            const float* wlr = s_wl + (kb + kk) * 64;
            const float* wrr = s_wr + (kb + kk) * 64;
#pragma unroll
            for (int j = 0; j < 64; j++) acc[j] += mv * wlr[j] + xv * wrr[j];
        }
    }

    float* o = g_h1 + (size_t)i * 64;
#pragma unroll
    for (int j = 0; j < 64; j += 4) {
        float4 v;
        v.x = fmaxf(acc[j + 0], 0.f);
        v.y = fmaxf(acc[j + 1], 0.f);
        v.z = fmaxf(acc[j + 2], 0.f);
        v.w = fmaxf(acc[j + 3], 0.f);
        *(float4*)(o + j) = v;
    }
}

// h2 = relu(mean2 @ w2_l + h1 @ w2_r + b2); then fused classifier:
// out = relu(h2 @ wc1 + bc1) @ wc2 + bc2  -> [N,2]
__global__ __launch_bounds__(128) void k_update2(const float* __restrict__ w2l,
                                                 const float* __restrict__ w2r,
                                                 const float* __restrict__ b2,
                                                 const float* __restrict__ wc1,
                                                 const float* __restrict__ bc1,
                                                 const float* __restrict__ wc2,
                                                 const float* __restrict__ bc2,
                                                 float* __restrict__ out) {
    __shared__ float s_wl[64 * 32], s_wr[64 * 32], s_b2[32];
    __shared__ float s_wc1[32 * 16], s_bc1[16], s_wc2[16 * 2], s_bc2[2];
    for (int idx = threadIdx.x; idx < 2048; idx += 128) {
        s_wl[idx] = w2l[idx];
        s_wr[idx] = w2r[idx];
    }
    for (int idx = threadIdx.x; idx < 512; idx += 128) s_wc1[idx] = wc1[idx];
    if (threadIdx.x < 32) s_b2[threadIdx.x]  = b2[threadIdx.x];
    if (threadIdx.x < 32) s_wc2[threadIdx.x] = wc2[threadIdx.x];
    if (threadIdx.x < 16) s_bc1[threadIdx.x] = bc1[threadIdx.x];
    if (threadIdx.x < 2)  s_bc2[threadIdx.x] = bc2[threadIdx.x];
    __syncthreads();

    int i = blockIdx.x * blockDim.x + threadIdx.x;
    if (i >= NN) return;
    const float* m  = g_mean + (size_t)i * 64;
    const float* hi = g_h1   + (size_t)i * 64;

    float acc[32];
#pragma unroll
    for (int j = 0; j < 32; j++) acc[j] = s_b2[j];

    for (int kb = 0; kb < 64; kb += 8) {
        float mr[8], xr[8];
        *(float4*)(mr)     = *(const float4*)(m + kb);
        *(float4*)(mr + 4) = *(const float4*)(m + kb + 4);
        *(float4*)(xr)     = *(const float4*)(hi + kb);
        *(float4*)(xr + 4) = *(const float4*)(hi + kb + 4);
#pragma unroll
        for (int kk = 0; kk < 8; kk++) {
            float mv = mr[kk], xv = xr[kk];
            const float* wlr = s_wl + (kb + kk) * 32;
            const float* wrr = s_wr + (kb + kk) * 32;
#pragma unroll
            for (int j = 0; j < 32; j++) acc[j] += mv * wlr[j] + xv * wrr[j];
        }
    }

    // classifier head, fully in registers
    float c1[16];
#pragma unroll
    for (int t = 0; t < 16; t++) c1[t] = s_bc1[t];
#pragma unroll
    for (int j = 0; j < 32; j++) {
        float h = fmaxf(acc[j], 0.f);
#pragma unroll
        for (int t = 0; t < 16; t++) c1[t] += h * s_wc1[j * 16 + t];
    }
    float o0 = s_bc2[0], o1 = s_bc2[1];
#pragma unroll
    for (int t = 0; t < 16; t++) {
        float h = fmaxf(c1[t], 0.f);
        o0 += h * s_wc2[t * 2 + 0];
        o1 += h * s_wc2[t * 2 + 1];
    }
    *(float2*)(out + (size_t)i * 2) = make_float2(o0, o1);
}

// ------------------------------------------------------------------- launch
extern "C" void kernel_launch(void* const* d_in, const int* in_sizes, int n_in,
                              void* d_out, int out_size) {
    const float* x   = (const float*)d_in[0];
    const int*   ei  = (const int*)d_in[1];
    const int*   src = ei;
    const int*   dst = ei + NE;
    const float* w1l = (const float*)d_in[2];
    const float* w1r = (const float*)d_in[3];
    const float* b1  = (const float*)d_in[4];
    const float* w2l = (const float*)d_in[5];
    const float* w2r = (const float*)d_in[6];
    const float* b2  = (const float*)d_in[7];
    const float* wc1 = (const float*)d_in[8];
    const float* bc1 = (const float*)d_in[9];
    const float* wc2 = (const float*)d_in[10];
    const float* bc2 = (const float*)d_in[11];
    float* out = (float*)d_out;

    // CSR build (per launch; graph-capturable, allocation-free)
    k_zero_counts<<<(NN + 255) / 256, 256>>>();
    k_hist<<<(NE + 255) / 256, 256>>>(dst);
    k_chunk_sums<<<NCHUNK, CHUNK>>>();
    k_scan_part<<<1, 128>>>();
    k_scan_chunks<<<NCHUNK, CHUNK>>>();
    k_scatter<<<(NE + 255) / 256, 256>>>(src, dst);

    // Layer 1
    k_aggregate1<<<(NN * 32 + 255) / 256, 256>>>(x);
    k_update1<<<(NN + 127) / 128, 128>>>(x, w1l, w1r, b1);

    // Layer 2 + classifier
    k_aggregate2<<<(NN * 32 + 255) / 256, 256>>>();
    k_update2<<<(NN + 127) / 128, 128>>>(w2l, w2r, b2, wc1, bc1, wc2, bc2, out);
}